// round 15
// baseline (speedup 1.0000x reference)
#include <cuda_runtime.h>
#include <cuda_fp16.h>
#include <math.h>

#define NMAX 100000
#define EMAX 3200000
#define F_IN 128
#define HID  16
#define NC   10
#define CPH  16   // layer-2 halfs per row (10 data + 6 pad) -> 32B, uint4-able

// ---- scratch (static device globals; no allocation allowed) ----
__device__ __align__(16) __half g_g1h[NMAX * HID];  // (x@W1)*dinv, fp16
__device__ __align__(16) __half g_g2h[NMAX * CPH];  // (h@W2)*dinv, fp16
__device__ float g_tmp1[NMAX * HID];   // gathered sums layer 1 (fp32)
__device__ float g_tmp2[NMAX * CPH];   // gathered sums layer 2 (fp32)
__device__ float g_dinv[NMAX];
__device__ int   g_cnt [NMAX];
__device__ int   g_cnt2[NMAX];         // placement cursors (init = base)
__device__ int   g_base[NMAX];
__device__ int   g_bsum[512];
__device__ int   g_csr [EMAX];

// ---------------------------------------------------------------
__global__ void zero_kernel(int n) {
    int i = blockIdx.x * blockDim.x + threadIdx.x;
    if (i < n) g_cnt[i] = 0;
}

__global__ void deg_kernel_v(const int* __restrict__ dst, int e) {
    int t = blockIdx.x * blockDim.x + threadIdx.x;
    int vecn = e >> 2;
    if (t < vecn) {
        int4 d4 = ((const int4*)dst)[t];
        atomicAdd(&g_cnt[d4.x], 1);
        atomicAdd(&g_cnt[d4.y], 1);
        atomicAdd(&g_cnt[d4.z], 1);
        atomicAdd(&g_cnt[d4.w], 1);
    } else {
        int i = (vecn << 2) + (t - vecn);
        if (i < e) atomicAdd(&g_cnt[dst[i]], 1);
    }
}
__global__ void deg_kernel_s(const int* __restrict__ dst, int e) {
    int i = blockIdx.x * blockDim.x + threadIdx.x;
    if (i < e) atomicAdd(&g_cnt[dst[i]], 1);
}

// ---- scan stage 1 (+ fused dinv) ----
__global__ __launch_bounds__(256) void scan1_kernel(int n) {
    __shared__ int wsum[8];
    int i = blockIdx.x * 256 + threadIdx.x;
    int lane = threadIdx.x & 31, warp = threadIdx.x >> 5;
    int v = (i < n) ? g_cnt[i] : 0;
    if (i < n) g_dinv[i] = rsqrtf((float)v + 1.0f);
    int s = v;
#pragma unroll
    for (int d = 16; d > 0; d >>= 1) s += __shfl_down_sync(~0u, s, d);
    if (lane == 0) wsum[warp] = s;
    __syncthreads();
    if (threadIdx.x == 0) {
        int t = 0;
#pragma unroll
        for (int w = 0; w < 8; ++w) t += wsum[w];
        g_bsum[blockIdx.x] = t;
    }
}

// ---- scan stage 2+3 fused -> g_base, cursor ----
__global__ __launch_bounds__(256) void scan3_kernel(int n) {
    __shared__ int wsum[8];
    __shared__ int wred[8];
    __shared__ int s_boff;
    int lane = threadIdx.x & 31, warp = threadIdx.x >> 5;

    int partial = 0;
    for (int j = threadIdx.x; j < blockIdx.x; j += 256) partial += g_bsum[j];
#pragma unroll
    for (int d = 16; d > 0; d >>= 1) partial += __shfl_down_sync(~0u, partial, d);
    if (lane == 0) wred[warp] = partial;
    __syncthreads();
    if (threadIdx.x == 0) {
        int t = 0;
#pragma unroll
        for (int w = 0; w < 8; ++w) t += wred[w];
        s_boff = t;
    }

    int i = blockIdx.x * 256 + threadIdx.x;
    int orig = (i < n) ? g_cnt[i] : 0;
    int v = orig;
#pragma unroll
    for (int d = 1; d < 32; d <<= 1) {
        int t = __shfl_up_sync(~0u, v, d);
        if (lane >= d) v += t;
    }
    if (lane == 31) wsum[warp] = v;
    __syncthreads();
    if (warp == 0 && lane < 8) {
        int s = wsum[lane];
#pragma unroll
        for (int d = 1; d < 8; d <<= 1) {
            int t = __shfl_up_sync(0xffu, s, d);
            if (lane >= d) s += t;
        }
        wsum[lane] = s;
    }
    __syncthreads();
    int wbase = (warp > 0) ? wsum[warp - 1] : 0;
    if (i < n) {
        int base = s_boff + wbase + v - orig;
        g_base[i] = base;
        g_cnt2[i] = base;
    }
}

// ---- CSR placement ----
__global__ void place_kernel_v(const int* __restrict__ src,
                               const int* __restrict__ dst, int e) {
    int t = blockIdx.x * blockDim.x + threadIdx.x;
    int vecn = e >> 2;
    if (t < vecn) {
        int4 s4 = ((const int4*)src)[t];
        int4 d4 = ((const int4*)dst)[t];
        g_csr[atomicAdd(&g_cnt2[d4.x], 1)] = s4.x;
        g_csr[atomicAdd(&g_cnt2[d4.y], 1)] = s4.y;
        g_csr[atomicAdd(&g_cnt2[d4.z], 1)] = s4.z;
        g_csr[atomicAdd(&g_cnt2[d4.w], 1)] = s4.w;
    } else {
        int i = (vecn << 2) + (t - vecn);
        if (i < e) g_csr[atomicAdd(&g_cnt2[dst[i]], 1)] = src[i];
    }
}
__global__ void place_kernel_s(const int* __restrict__ src,
                               const int* __restrict__ dst, int e) {
    int i = blockIdx.x * blockDim.x + threadIdx.x;
    if (i < e) g_csr[atomicAdd(&g_cnt2[dst[i]], 1)] = src[i];
}

// ---- GEMM1: g1h = fp16((x @ W1) * dinv) (warp-staged) ----
__global__ __launch_bounds__(256) void gemm1_kernel(const float* __restrict__ x,
                                                    const float* __restrict__ W1,
                                                    int n) {
    __shared__ float w1s[F_IN * HID];
    __shared__ float xs[8][32][33];
#pragma unroll
    for (int i = threadIdx.x; i < F_IN * HID; i += 256)
        w1s[i] = W1[i];
    __syncthreads();

    const int warp = threadIdx.x >> 5;
    const int lane = threadIdx.x & 31;
    const int row0 = blockIdx.x * 256 + warp * 32;
    const int myrow = row0 + lane;

    float acc[16];
#pragma unroll
    for (int o = 0; o < 16; ++o) acc[o] = 0.f;

#pragma unroll 1
    for (int kc = 0; kc < 4; ++kc) {
#pragma unroll 8
        for (int r = 0; r < 32; ++r) {
            int row = row0 + r;
            xs[warp][r][lane] = (row < n)
                ? x[(size_t)row * F_IN + kc * 32 + lane] : 0.f;
        }
        __syncwarp();
#pragma unroll
        for (int k = 0; k < 32; ++k) {
            float xv = xs[warp][lane][k];
            const float* w = w1s + (kc * 32 + k) * HID;
            float4 wa = *(const float4*)(w + 0);
            float4 wb = *(const float4*)(w + 4);
            float4 wc = *(const float4*)(w + 8);
            float4 wd = *(const float4*)(w + 12);
            acc[0]  = fmaf(xv, wa.x, acc[0]);  acc[1]  = fmaf(xv, wa.y, acc[1]);
            acc[2]  = fmaf(xv, wa.z, acc[2]);  acc[3]  = fmaf(xv, wa.w, acc[3]);
            acc[4]  = fmaf(xv, wb.x, acc[4]);  acc[5]  = fmaf(xv, wb.y, acc[5]);
            acc[6]  = fmaf(xv, wb.z, acc[6]);  acc[7]  = fmaf(xv, wb.w, acc[7]);
            acc[8]  = fmaf(xv, wc.x, acc[8]);  acc[9]  = fmaf(xv, wc.y, acc[9]);
            acc[10] = fmaf(xv, wc.z, acc[10]); acc[11] = fmaf(xv, wc.w, acc[11]);
            acc[12] = fmaf(xv, wd.x, acc[12]); acc[13] = fmaf(xv, wd.y, acc[13]);
            acc[14] = fmaf(xv, wd.z, acc[14]); acc[15] = fmaf(xv, wd.w, acc[15]);
        }
        __syncwarp();
    }

    if (myrow < n) {
        float dv = g_dinv[myrow];
        __half2 h[8];
#pragma unroll
        for (int o = 0; o < 8; ++o)
            h[o] = __floats2half2_rn(acc[o * 2] * dv, acc[o * 2 + 1] * dv);
        uint4* out = (uint4*)(g_g1h + (size_t)myrow * HID);
        out[0] = *(uint4*)&h[0];
        out[1] = *(uint4*)&h[4];
    }
}

// ---- gather: warp per node, 2 lanes per edge, uint4 (8-half) loads,
// fp32 accumulate, butterfly over strides 2/4/8/16 (q=lane&1 preserved),
// lanes 0-1 write the fp32 tmp half-rows. Both layers stride 16 halfs. ----
template <int LAYER>
__global__ __launch_bounds__(256) void gather_kernel(int n) {
    const __half* __restrict__ in = (LAYER == 0) ? g_g1h : g_g2h;
    float* __restrict__ out       = (LAYER == 0) ? g_tmp1 : g_tmp2;

    int gw = (blockIdx.x * 256 + threadIdx.x) >> 5;
    if (gw >= n) return;
    int lane = threadIdx.x & 31;
    int eq = lane >> 1, q = lane & 1;
    int m = g_cnt[gw];
    const int* cs = g_csr + g_base[gw];

    float acc[8];
#pragma unroll
    for (int i = 0; i < 8; ++i) acc[i] = 0.f;

    int j = eq;
    for (; j + 16 < m; j += 32) {
        int s0 = cs[j], s1 = cs[j + 16];
        uint4 va = *(const uint4*)(in + (size_t)s0 * 16 + q * 8);
        uint4 vb = *(const uint4*)(in + (size_t)s1 * 16 + q * 8);
        float2 f;
        f = __half22float2(*(const __half2*)&va.x); acc[0] += f.x; acc[1] += f.y;
        f = __half22float2(*(const __half2*)&va.y); acc[2] += f.x; acc[3] += f.y;
        f = __half22float2(*(const __half2*)&va.z); acc[4] += f.x; acc[5] += f.y;
        f = __half22float2(*(const __half2*)&va.w); acc[6] += f.x; acc[7] += f.y;
        f = __half22float2(*(const __half2*)&vb.x); acc[0] += f.x; acc[1] += f.y;
        f = __half22float2(*(const __half2*)&vb.y); acc[2] += f.x; acc[3] += f.y;
        f = __half22float2(*(const __half2*)&vb.z); acc[4] += f.x; acc[5] += f.y;
        f = __half22float2(*(const __half2*)&vb.w); acc[6] += f.x; acc[7] += f.y;
    }
    for (; j < m; j += 16) {
        int s = cs[j];
        uint4 va = *(const uint4*)(in + (size_t)s * 16 + q * 8);
        float2 f;
        f = __half22float2(*(const __half2*)&va.x); acc[0] += f.x; acc[1] += f.y;
        f = __half22float2(*(const __half2*)&va.y); acc[2] += f.x; acc[3] += f.y;
        f = __half22float2(*(const __half2*)&va.z); acc[4] += f.x; acc[5] += f.y;
        f = __half22float2(*(const __half2*)&va.w); acc[6] += f.x; acc[7] += f.y;
    }
#pragma unroll
    for (int st = 2; st < 32; st <<= 1) {
#pragma unroll
        for (int i = 0; i < 8; ++i)
            acc[i] += __shfl_xor_sync(~0u, acc[i], st);
    }
    if (lane < 2) {
        float* o = out + (size_t)gw * 16 + q * 8;
        ((float4*)o)[0] = make_float4(acc[0], acc[1], acc[2], acc[3]);
        ((float4*)o)[1] = make_float4(acc[4], acc[5], acc[6], acc[7]);
    }
}

// ---- finalize layer1 + GEMM2: h=relu(dinv*(tmp1+g1)+b1); g2h=fp16((h@W2)*dinv) ----
__global__ __launch_bounds__(256) void fin1_kernel(const float* __restrict__ b1,
                                                   const float* __restrict__ W2,
                                                   int n) {
    __shared__ float w2s[HID * NC];
    __shared__ float b1s[HID];
    int tid = threadIdx.x;
    if (tid < HID * NC) w2s[tid] = W2[tid];
    if (tid < HID)      b1s[tid] = b1[tid];
    __syncthreads();

    int i = blockIdx.x * 256 + tid;
    if (i >= n) return;
    float dv = g_dinv[i];

    float h[16];
    const float4* tp = (const float4*)(g_tmp1 + (size_t)i * HID);
    const __half2* gp = (const __half2*)(g_g1h + (size_t)i * HID);
#pragma unroll
    for (int o4 = 0; o4 < 4; ++o4) {
        float4 t = tp[o4];
        float2 ga = __half22float2(gp[o4 * 2]);
        float2 gb = __half22float2(gp[o4 * 2 + 1]);
        h[o4 * 4 + 0] = fmaxf(fmaf(dv, t.x + ga.x, b1s[o4 * 4 + 0]), 0.f);
        h[o4 * 4 + 1] = fmaxf(fmaf(dv, t.y + ga.y, b1s[o4 * 4 + 1]), 0.f);
        h[o4 * 4 + 2] = fmaxf(fmaf(dv, t.z + gb.x, b1s[o4 * 4 + 2]), 0.f);
        h[o4 * 4 + 3] = fmaxf(fmaf(dv, t.w + gb.y, b1s[o4 * 4 + 3]), 0.f);
    }

    float acc[NC];
#pragma unroll
    for (int c = 0; c < NC; ++c) acc[c] = 0.f;
#pragma unroll
    for (int o = 0; o < HID; ++o) {
        float hv = h[o];
#pragma unroll
        for (int c = 0; c < NC; ++c) acc[c] = fmaf(hv, w2s[o * NC + c], acc[c]);
    }

    __half2 p[8];
#pragma unroll
    for (int c = 0; c < 5; ++c)
        p[c] = __floats2half2_rn(acc[c * 2] * dv, acc[c * 2 + 1] * dv);
    p[5] = __floats2half2_rn(0.f, 0.f);
    p[6] = p[5]; p[7] = p[5];
    uint4* out = (uint4*)(g_g2h + (size_t)i * CPH);
    out[0] = *(uint4*)&p[0];
    out[1] = *(uint4*)&p[4];
}

// ---- finalize layer2 + softmax ----
__global__ __launch_bounds__(256) void fin2_kernel(const float* __restrict__ b2,
                                                   float* __restrict__ out, int n) {
    __shared__ float b2s[NC];
    if (threadIdx.x < NC) b2s[threadIdx.x] = b2[threadIdx.x];
    __syncthreads();
    int i = blockIdx.x * blockDim.x + threadIdx.x;
    if (i >= n) return;
    float dv = g_dinv[i];
    const float* tp = g_tmp2 + (size_t)i * CPH;
    const __half2* gp = (const __half2*)(g_g2h + (size_t)i * CPH);
    float g[10];
#pragma unroll
    for (int c = 0; c < 5; ++c) {
        float2 f = __half22float2(gp[c]);
        g[c * 2] = f.x; g[c * 2 + 1] = f.y;
    }
    float l[NC];
    float m = -1e30f;
#pragma unroll
    for (int c = 0; c < NC; ++c) {
        l[c] = fmaf(dv, tp[c] + g[c], b2s[c]);
        m = fmaxf(m, l[c]);
    }
    float sum = 0.f;
#pragma unroll
    for (int c = 0; c < NC; ++c) {
        l[c] = expf(l[c] - m);
        sum += l[c];
    }
    float inv = 1.0f / sum;
#pragma unroll
    for (int c = 0; c < NC; ++c) out[i * NC + c] = l[c] * inv;
}

// ---------------------------------------------------------------
extern "C" void kernel_launch(void* const* d_in, const int* in_sizes, int n_in,
                              void* d_out, int out_size) {
    const float* x  = (const float*)d_in[0];
    const int*   ei = (const int*)  d_in[1];
    const float* W1 = (const float*)d_in[2];
    const float* b1 = (const float*)d_in[3];
    const float* W2 = (const float*)d_in[4];
    const float* b2 = (const float*)d_in[5];
    float* out = (float*)d_out;

    int n = in_sizes[0] / F_IN;
    int e = in_sizes[1] / 2;
    const int* src = ei;
    const int* dst = ei + e;
    int nb = (n + 255) / 256;

    bool aligned = ((e & 3) == 0) &&
                   ((((size_t)src) & 15) == 0) && ((((size_t)dst) & 15) == 0);

    zero_kernel <<<nb, 256>>>(n);
    if (aligned) {
        int t = (e >> 2);
        deg_kernel_v<<<(t + 255) / 256, 256>>>(dst, e);
    } else {
        deg_kernel_s<<<(e + 255) / 256, 256>>>(dst, e);
    }
    scan1_kernel<<<nb, 256>>>(n);
    scan3_kernel<<<nb, 256>>>(n);
    if (aligned) {
        int t = (e >> 2);
        place_kernel_v<<<(t + 255) / 256, 256>>>(src, dst, e);
    } else {
        place_kernel_s<<<(e + 255) / 256, 256>>>(src, dst, e);
    }
    gemm1_kernel<<<nb, 256>>>(x, W1, n);
    gather_kernel<0><<<(n * 32 + 255) / 256, 256>>>(n);
    fin1_kernel <<<nb, 256>>>(b1, W2, n);
    gather_kernel<1><<<(n * 32 + 255) / 256, 256>>>(n);
    fin2_kernel <<<nb, 256>>>(b2, out, n);
}

// round 16
// speedup vs baseline: 1.0913x; 1.0913x over previous
#include <cuda_runtime.h>
#include <cuda_fp16.h>
#include <math.h>

#define NMAX 100000
#define EMAX 3200000
#define F_IN 128
#define HID  16
#define NC   10
#define CPH  12   // layer-2 halfs per row: 10 + 2 pad = 24B, 8B-aligned rows

// ---- scratch (static device globals; no allocation allowed) ----
__device__ __align__(16) __half g_g1h[NMAX * HID];  // (x@W1)*dinv, fp16
__device__ __align__(16) __half g_g2h[NMAX * CPH];  // (h@W2)*dinv, fp16
__device__ float g_tmp1[NMAX * HID];   // gathered sums layer 1 (fp32)
__device__ float g_tmp2[NMAX * CPH];   // gathered sums layer 2 (fp32)
__device__ float g_dinv[NMAX];
__device__ int   g_cnt [NMAX];
__device__ int   g_cnt2[NMAX];         // placement cursors (init = base)
__device__ int   g_base[NMAX];
__device__ int   g_bsum[512];
__device__ int   g_csr [EMAX];

// ---------------------------------------------------------------
__global__ void zero_kernel(int n) {
    int i = blockIdx.x * blockDim.x + threadIdx.x;
    if (i < n) g_cnt[i] = 0;
}

__global__ void deg_kernel_v(const int* __restrict__ dst, int e) {
    int t = blockIdx.x * blockDim.x + threadIdx.x;
    int vecn = e >> 2;
    if (t < vecn) {
        int4 d4 = ((const int4*)dst)[t];
        atomicAdd(&g_cnt[d4.x], 1);
        atomicAdd(&g_cnt[d4.y], 1);
        atomicAdd(&g_cnt[d4.z], 1);
        atomicAdd(&g_cnt[d4.w], 1);
    } else {
        int i = (vecn << 2) + (t - vecn);
        if (i < e) atomicAdd(&g_cnt[dst[i]], 1);
    }
}
__global__ void deg_kernel_s(const int* __restrict__ dst, int e) {
    int i = blockIdx.x * blockDim.x + threadIdx.x;
    if (i < e) atomicAdd(&g_cnt[dst[i]], 1);
}

// ---- scan stage 1 (+ fused dinv) ----
__global__ __launch_bounds__(256) void scan1_kernel(int n) {
    __shared__ int wsum[8];
    int i = blockIdx.x * 256 + threadIdx.x;
    int lane = threadIdx.x & 31, warp = threadIdx.x >> 5;
    int v = (i < n) ? g_cnt[i] : 0;
    if (i < n) g_dinv[i] = rsqrtf((float)v + 1.0f);
    int s = v;
#pragma unroll
    for (int d = 16; d > 0; d >>= 1) s += __shfl_down_sync(~0u, s, d);
    if (lane == 0) wsum[warp] = s;
    __syncthreads();
    if (threadIdx.x == 0) {
        int t = 0;
#pragma unroll
        for (int w = 0; w < 8; ++w) t += wsum[w];
        g_bsum[blockIdx.x] = t;
    }
}

// ---- scan stage 2+3 fused -> g_base, cursor ----
__global__ __launch_bounds__(256) void scan3_kernel(int n) {
    __shared__ int wsum[8];
    __shared__ int wred[8];
    __shared__ int s_boff;
    int lane = threadIdx.x & 31, warp = threadIdx.x >> 5;

    int partial = 0;
    for (int j = threadIdx.x; j < blockIdx.x; j += 256) partial += g_bsum[j];
#pragma unroll
    for (int d = 16; d > 0; d >>= 1) partial += __shfl_down_sync(~0u, partial, d);
    if (lane == 0) wred[warp] = partial;
    __syncthreads();
    if (threadIdx.x == 0) {
        int t = 0;
#pragma unroll
        for (int w = 0; w < 8; ++w) t += wred[w];
        s_boff = t;
    }

    int i = blockIdx.x * 256 + threadIdx.x;
    int orig = (i < n) ? g_cnt[i] : 0;
    int v = orig;
#pragma unroll
    for (int d = 1; d < 32; d <<= 1) {
        int t = __shfl_up_sync(~0u, v, d);
        if (lane >= d) v += t;
    }
    if (lane == 31) wsum[warp] = v;
    __syncthreads();
    if (warp == 0 && lane < 8) {
        int s = wsum[lane];
#pragma unroll
        for (int d = 1; d < 8; d <<= 1) {
            int t = __shfl_up_sync(0xffu, s, d);
            if (lane >= d) s += t;
        }
        wsum[lane] = s;
    }
    __syncthreads();
    int wbase = (warp > 0) ? wsum[warp - 1] : 0;
    if (i < n) {
        int base = s_boff + wbase + v - orig;
        g_base[i] = base;
        g_cnt2[i] = base;
    }
}

// ---- CSR placement ----
__global__ void place_kernel_v(const int* __restrict__ src,
                               const int* __restrict__ dst, int e) {
    int t = blockIdx.x * blockDim.x + threadIdx.x;
    int vecn = e >> 2;
    if (t < vecn) {
        int4 s4 = ((const int4*)src)[t];
        int4 d4 = ((const int4*)dst)[t];
        g_csr[atomicAdd(&g_cnt2[d4.x], 1)] = s4.x;
        g_csr[atomicAdd(&g_cnt2[d4.y], 1)] = s4.y;
        g_csr[atomicAdd(&g_cnt2[d4.z], 1)] = s4.z;
        g_csr[atomicAdd(&g_cnt2[d4.w], 1)] = s4.w;
    } else {
        int i = (vecn << 2) + (t - vecn);
        if (i < e) g_csr[atomicAdd(&g_cnt2[dst[i]], 1)] = src[i];
    }
}
__global__ void place_kernel_s(const int* __restrict__ src,
                               const int* __restrict__ dst, int e) {
    int i = blockIdx.x * blockDim.x + threadIdx.x;
    if (i < e) g_csr[atomicAdd(&g_cnt2[dst[i]], 1)] = src[i];
}

// ---- GEMM1: g1h = fp16((x @ W1) * dinv) (warp-staged) ----
__global__ __launch_bounds__(256) void gemm1_kernel(const float* __restrict__ x,
                                                    const float* __restrict__ W1,
                                                    int n) {
    __shared__ float w1s[F_IN * HID];
    __shared__ float xs[8][32][33];
#pragma unroll
    for (int i = threadIdx.x; i < F_IN * HID; i += 256)
        w1s[i] = W1[i];
    __syncthreads();

    const int warp = threadIdx.x >> 5;
    const int lane = threadIdx.x & 31;
    const int row0 = blockIdx.x * 256 + warp * 32;
    const int myrow = row0 + lane;

    float acc[16];
#pragma unroll
    for (int o = 0; o < 16; ++o) acc[o] = 0.f;

#pragma unroll 1
    for (int kc = 0; kc < 4; ++kc) {
#pragma unroll 8
        for (int r = 0; r < 32; ++r) {
            int row = row0 + r;
            xs[warp][r][lane] = (row < n)
                ? x[(size_t)row * F_IN + kc * 32 + lane] : 0.f;
        }
        __syncwarp();
#pragma unroll
        for (int k = 0; k < 32; ++k) {
            float xv = xs[warp][lane][k];
            const float* w = w1s + (kc * 32 + k) * HID;
            float4 wa = *(const float4*)(w + 0);
            float4 wb = *(const float4*)(w + 4);
            float4 wc = *(const float4*)(w + 8);
            float4 wd = *(const float4*)(w + 12);
            acc[0]  = fmaf(xv, wa.x, acc[0]);  acc[1]  = fmaf(xv, wa.y, acc[1]);
            acc[2]  = fmaf(xv, wa.z, acc[2]);  acc[3]  = fmaf(xv, wa.w, acc[3]);
            acc[4]  = fmaf(xv, wb.x, acc[4]);  acc[5]  = fmaf(xv, wb.y, acc[5]);
            acc[6]  = fmaf(xv, wb.z, acc[6]);  acc[7]  = fmaf(xv, wb.w, acc[7]);
            acc[8]  = fmaf(xv, wc.x, acc[8]);  acc[9]  = fmaf(xv, wc.y, acc[9]);
            acc[10] = fmaf(xv, wc.z, acc[10]); acc[11] = fmaf(xv, wc.w, acc[11]);
            acc[12] = fmaf(xv, wd.x, acc[12]); acc[13] = fmaf(xv, wd.y, acc[13]);
            acc[14] = fmaf(xv, wd.z, acc[14]); acc[15] = fmaf(xv, wd.w, acc[15]);
        }
        __syncwarp();
    }

    if (myrow < n) {
        float dv = g_dinv[myrow];
        __half2 h[8];
#pragma unroll
        for (int o = 0; o < 8; ++o)
            h[o] = __floats2half2_rn(acc[o * 2] * dv, acc[o * 2 + 1] * dv);
        uint4* out = (uint4*)(g_g1h + (size_t)myrow * HID);
        out[0] = *(uint4*)&h[0];
        out[1] = *(uint4*)&h[4];
    }
}

// ---- gather: warp per node, 4-lane edge groups over fp16 rows, 4-deep
// independent loads per lane (MLP=4), fp32 accumulate, butterfly reduce.
// LAYER 0: 16 halfs (32B) rows, 4 quarters. LAYER 1: 12 halfs (24B), 3 q. ----
template <int LAYER>
__global__ __launch_bounds__(256) void gather_kernel(int n) {
    const __half* __restrict__ in = (LAYER == 0) ? g_g1h : g_g2h;
    float* __restrict__ out       = (LAYER == 0) ? g_tmp1 : g_tmp2;
    const int stride = (LAYER == 0) ? HID : CPH;  // halfs per row
    const int nq     = (LAYER == 0) ? 4 : 3;

    int gw = (blockIdx.x * 256 + threadIdx.x) >> 5;
    if (gw >= n) return;
    int lane = threadIdx.x & 31;
    int eq = lane >> 2, q = lane & 3;
    int m = g_cnt[gw];
    const int* cs = g_csr + g_base[gw];

    float4 acc = make_float4(0.f, 0.f, 0.f, 0.f);
    if (q < nq) {
        int j = eq;
        for (; j + 24 < m; j += 32) {
            int s0 = cs[j], s1 = cs[j + 8], s2 = cs[j + 16], s3 = cs[j + 24];
            uint2 v0 = *(const uint2*)(in + (size_t)s0 * stride + q * 4);
            uint2 v1 = *(const uint2*)(in + (size_t)s1 * stride + q * 4);
            uint2 v2 = *(const uint2*)(in + (size_t)s2 * stride + q * 4);
            uint2 v3 = *(const uint2*)(in + (size_t)s3 * stride + q * 4);
            float2 f;
            f = __half22float2(*(const __half2*)&v0.x); acc.x += f.x; acc.y += f.y;
            f = __half22float2(*(const __half2*)&v0.y); acc.z += f.x; acc.w += f.y;
            f = __half22float2(*(const __half2*)&v1.x); acc.x += f.x; acc.y += f.y;
            f = __half22float2(*(const __half2*)&v1.y); acc.z += f.x; acc.w += f.y;
            f = __half22float2(*(const __half2*)&v2.x); acc.x += f.x; acc.y += f.y;
            f = __half22float2(*(const __half2*)&v2.y); acc.z += f.x; acc.w += f.y;
            f = __half22float2(*(const __half2*)&v3.x); acc.x += f.x; acc.y += f.y;
            f = __half22float2(*(const __half2*)&v3.y); acc.z += f.x; acc.w += f.y;
        }
        for (; j < m; j += 8) {
            int s = cs[j];
            uint2 va = *(const uint2*)(in + (size_t)s * stride + q * 4);
            float2 f;
            f = __half22float2(*(const __half2*)&va.x); acc.x += f.x; acc.y += f.y;
            f = __half22float2(*(const __half2*)&va.y); acc.z += f.x; acc.w += f.y;
        }
    }
#pragma unroll
    for (int st = 4; st < 32; st <<= 1) {
        acc.x += __shfl_xor_sync(~0u, acc.x, st);
        acc.y += __shfl_xor_sync(~0u, acc.y, st);
        acc.z += __shfl_xor_sync(~0u, acc.z, st);
        acc.w += __shfl_xor_sync(~0u, acc.w, st);
    }
    if (lane < nq)
        *(float4*)(out + (size_t)gw * stride + q * 4) = acc;
}

// ---- finalize layer1 + GEMM2: h=relu(dinv*(tmp1+g1)+b1); g2h=fp16((h@W2)*dinv) ----
__global__ __launch_bounds__(256) void fin1_kernel(const float* __restrict__ b1,
                                                   const float* __restrict__ W2,
                                                   int n) {
    __shared__ float w2s[HID * NC];
    __shared__ float b1s[HID];
    int tid = threadIdx.x;
    if (tid < HID * NC) w2s[tid] = W2[tid];
    if (tid < HID)      b1s[tid] = b1[tid];
    __syncthreads();

    int i = blockIdx.x * 256 + tid;
    if (i >= n) return;
    float dv = g_dinv[i];

    float h[16];
    const float4* tp = (const float4*)(g_tmp1 + (size_t)i * HID);
    const __half2* gp = (const __half2*)(g_g1h + (size_t)i * HID);
#pragma unroll
    for (int o4 = 0; o4 < 4; ++o4) {
        float4 t = tp[o4];
        float2 ga = __half22float2(gp[o4 * 2]);
        float2 gb = __half22float2(gp[o4 * 2 + 1]);
        h[o4 * 4 + 0] = fmaxf(fmaf(dv, t.x + ga.x, b1s[o4 * 4 + 0]), 0.f);
        h[o4 * 4 + 1] = fmaxf(fmaf(dv, t.y + ga.y, b1s[o4 * 4 + 1]), 0.f);
        h[o4 * 4 + 2] = fmaxf(fmaf(dv, t.z + gb.x, b1s[o4 * 4 + 2]), 0.f);
        h[o4 * 4 + 3] = fmaxf(fmaf(dv, t.w + gb.y, b1s[o4 * 4 + 3]), 0.f);
    }

    float acc[NC];
#pragma unroll
    for (int c = 0; c < NC; ++c) acc[c] = 0.f;
#pragma unroll
    for (int o = 0; o < HID; ++o) {
        float hv = h[o];
#pragma unroll
        for (int c = 0; c < NC; ++c) acc[c] = fmaf(hv, w2s[o * NC + c], acc[c]);
    }

    __half2 p[6];
#pragma unroll
    for (int c = 0; c < 5; ++c)
        p[c] = __floats2half2_rn(acc[c * 2] * dv, acc[c * 2 + 1] * dv);
    p[5] = __floats2half2_rn(0.f, 0.f);
    uint2* out = (uint2*)(g_g2h + (size_t)i * CPH);
    out[0] = *(uint2*)&p[0];
    out[1] = *(uint2*)&p[2];
    out[2] = *(uint2*)&p[4];
}

// ---- finalize layer2 + softmax ----
__global__ __launch_bounds__(256) void fin2_kernel(const float* __restrict__ b2,
                                                   float* __restrict__ out, int n) {
    __shared__ float b2s[NC];
    if (threadIdx.x < NC) b2s[threadIdx.x] = b2[threadIdx.x];
    __syncthreads();
    int i = blockIdx.x * blockDim.x + threadIdx.x;
    if (i >= n) return;
    float dv = g_dinv[i];
    const float* tp = g_tmp2 + (size_t)i * CPH;
    const __half2* gp = (const __half2*)(g_g2h + (size_t)i * CPH);
    float g[10];
#pragma unroll
    for (int c = 0; c < 5; ++c) {
        float2 f = __half22float2(gp[c]);
        g[c * 2] = f.x; g[c * 2 + 1] = f.y;
    }
    float l[NC];
    float m = -1e30f;
#pragma unroll
    for (int c = 0; c < NC; ++c) {
        l[c] = fmaf(dv, tp[c] + g[c], b2s[c]);
        m = fmaxf(m, l[c]);
    }
    float sum = 0.f;
#pragma unroll
    for (int c = 0; c < NC; ++c) {
        l[c] = expf(l[c] - m);
        sum += l[c];
    }
    float inv = 1.0f / sum;
#pragma unroll
    for (int c = 0; c < NC; ++c) out[i * NC + c] = l[c] * inv;
}

// ---------------------------------------------------------------
extern "C" void kernel_launch(void* const* d_in, const int* in_sizes, int n_in,
                              void* d_out, int out_size) {
    const float* x  = (const float*)d_in[0];
    const int*   ei = (const int*)  d_in[1];
    const float* W1 = (const float*)d_in[2];
    const float* b1 = (const float*)d_in[3];
    const float* W2 = (const float*)d_in[4];
    const float* b2 = (const float*)d_in[5];
    float* out = (float*)d_out;

    int n = in_sizes[0] / F_IN;
    int e = in_sizes[1] / 2;
    const int* src = ei;
    const int* dst = ei + e;
    int nb = (n + 255) / 256;

    bool aligned = ((e & 3) == 0) &&
                   ((((size_t)src) & 15) == 0) && ((((size_t)dst) & 15) == 0);

    zero_kernel <<<nb, 256>>>(n);
    if (aligned) {
        int t = (e >> 2);
        deg_kernel_v<<<(t + 255) / 256, 256>>>(dst, e);
    } else {
        deg_kernel_s<<<(e + 255) / 256, 256>>>(dst, e);
    }
    scan1_kernel<<<nb, 256>>>(n);
    scan3_kernel<<<nb, 256>>>(n);
    if (aligned) {
        int t = (e >> 2);
        place_kernel_v<<<(t + 255) / 256, 256>>>(src, dst, e);
    } else {
        place_kernel_s<<<(e + 255) / 256, 256>>>(src, dst, e);
    }
    gemm1_kernel<<<nb, 256>>>(x, W1, n);
    gather_kernel<0><<<(n * 32 + 255) / 256, 256>>>(n);
    fin1_kernel <<<nb, 256>>>(b1, W2, n);
    gather_kernel<1><<<(n * 32 + 255) / 256, 256>>>(n);
    fin2_kernel <<<nb, 256>>>(b2, out, n);
}

// round 17
// speedup vs baseline: 1.1202x; 1.0265x over previous
#include <cuda_runtime.h>
#include <cuda_fp16.h>
#include <math.h>

#define NMAX 100000
#define EMAX 3200000
#define F_IN 128
#define HID  16
#define NC   10
#define CPH  12   // layer-2 halfs per row: 10 + 2 pad = 24B, 8B-aligned rows

// ---- scratch (static device globals; no allocation allowed) ----
__device__ __align__(16) __half g_g1h[NMAX * HID];  // (x@W1)*dinv, fp16
__device__ __align__(16) __half g_g2h[NMAX * CPH];  // (h@W2)*dinv, fp16
__device__ float g_tmp1[NMAX * HID];   // gathered sums layer 1 (fp32)
__device__ float g_tmp2[NMAX * CPH];   // gathered sums layer 2 (fp32)
__device__ float g_dinv[NMAX];
__device__ int   g_cnt [NMAX];
__device__ int   g_cnt2[NMAX];         // placement cursors (init = base)
__device__ int   g_base[NMAX];
__device__ int   g_bsum[512];
__device__ int   g_csr [EMAX];

// ---------------------------------------------------------------
__global__ void zero_kernel(int n) {
    int i = blockIdx.x * blockDim.x + threadIdx.x;
    if (i < n) g_cnt[i] = 0;
}

__global__ void deg_kernel_v(const int* __restrict__ dst, int e) {
    int t = blockIdx.x * blockDim.x + threadIdx.x;
    int vecn = e >> 2;
    if (t < vecn) {
        int4 d4 = ((const int4*)dst)[t];
        atomicAdd(&g_cnt[d4.x], 1);
        atomicAdd(&g_cnt[d4.y], 1);
        atomicAdd(&g_cnt[d4.z], 1);
        atomicAdd(&g_cnt[d4.w], 1);
    } else {
        int i = (vecn << 2) + (t - vecn);
        if (i < e) atomicAdd(&g_cnt[dst[i]], 1);
    }
}
__global__ void deg_kernel_s(const int* __restrict__ dst, int e) {
    int i = blockIdx.x * blockDim.x + threadIdx.x;
    if (i < e) atomicAdd(&g_cnt[dst[i]], 1);
}

// ---- scan stage 1 (+ fused dinv) ----
__global__ __launch_bounds__(256) void scan1_kernel(int n) {
    __shared__ int wsum[8];
    int i = blockIdx.x * 256 + threadIdx.x;
    int lane = threadIdx.x & 31, warp = threadIdx.x >> 5;
    int v = (i < n) ? g_cnt[i] : 0;
    if (i < n) g_dinv[i] = rsqrtf((float)v + 1.0f);
    int s = v;
#pragma unroll
    for (int d = 16; d > 0; d >>= 1) s += __shfl_down_sync(~0u, s, d);
    if (lane == 0) wsum[warp] = s;
    __syncthreads();
    if (threadIdx.x == 0) {
        int t = 0;
#pragma unroll
        for (int w = 0; w < 8; ++w) t += wsum[w];
        g_bsum[blockIdx.x] = t;
    }
}

// ---- scan stage 2+3 fused -> g_base, cursor ----
__global__ __launch_bounds__(256) void scan3_kernel(int n) {
    __shared__ int wsum[8];
    __shared__ int wred[8];
    __shared__ int s_boff;
    int lane = threadIdx.x & 31, warp = threadIdx.x >> 5;

    int partial = 0;
    for (int j = threadIdx.x; j < blockIdx.x; j += 256) partial += g_bsum[j];
#pragma unroll
    for (int d = 16; d > 0; d >>= 1) partial += __shfl_down_sync(~0u, partial, d);
    if (lane == 0) wred[warp] = partial;
    __syncthreads();
    if (threadIdx.x == 0) {
        int t = 0;
#pragma unroll
        for (int w = 0; w < 8; ++w) t += wred[w];
        s_boff = t;
    }

    int i = blockIdx.x * 256 + threadIdx.x;
    int orig = (i < n) ? g_cnt[i] : 0;
    int v = orig;
#pragma unroll
    for (int d = 1; d < 32; d <<= 1) {
        int t = __shfl_up_sync(~0u, v, d);
        if (lane >= d) v += t;
    }
    if (lane == 31) wsum[warp] = v;
    __syncthreads();
    if (warp == 0 && lane < 8) {
        int s = wsum[lane];
#pragma unroll
        for (int d = 1; d < 8; d <<= 1) {
            int t = __shfl_up_sync(0xffu, s, d);
            if (lane >= d) s += t;
        }
        wsum[lane] = s;
    }
    __syncthreads();
    int wbase = (warp > 0) ? wsum[warp - 1] : 0;
    if (i < n) {
        int base = s_boff + wbase + v - orig;
        g_base[i] = base;
        g_cnt2[i] = base;
    }
}

// ---- CSR placement ----
__global__ void place_kernel_v(const int* __restrict__ src,
                               const int* __restrict__ dst, int e) {
    int t = blockIdx.x * blockDim.x + threadIdx.x;
    int vecn = e >> 2;
    if (t < vecn) {
        int4 s4 = ((const int4*)src)[t];
        int4 d4 = ((const int4*)dst)[t];
        g_csr[atomicAdd(&g_cnt2[d4.x], 1)] = s4.x;
        g_csr[atomicAdd(&g_cnt2[d4.y], 1)] = s4.y;
        g_csr[atomicAdd(&g_cnt2[d4.z], 1)] = s4.z;
        g_csr[atomicAdd(&g_cnt2[d4.w], 1)] = s4.w;
    } else {
        int i = (vecn << 2) + (t - vecn);
        if (i < e) g_csr[atomicAdd(&g_cnt2[dst[i]], 1)] = src[i];
    }
}
__global__ void place_kernel_s(const int* __restrict__ src,
                               const int* __restrict__ dst, int e) {
    int i = blockIdx.x * blockDim.x + threadIdx.x;
    if (i < e) g_csr[atomicAdd(&g_cnt2[dst[i]], 1)] = src[i];
}

// ---- GEMM1 via mma.sync m16n8k16: g1h = fp16((x @ W1) * dinv).
// One warp per 16-row tile. x staged to smem fp16 (stride 136 halfs ->
// conflict-free fragment loads). W1 in smem fp16; B fragments preloaded
// to registers (8 k-steps x 2 n-tiles). fp32 accumulators. ----
__global__ __launch_bounds__(256) void gemm1_kernel(const float* __restrict__ x,
                                                    const float* __restrict__ W1,
                                                    int n) {
    __shared__ __half w1h[F_IN * HID];        // 4 KB
    __shared__ __half xs[8][16 * 136];        // 8 warps x 4352 B = 34 KB
    const int tid = threadIdx.x;

    for (int i = tid; i < F_IN * HID; i += 256)
        w1h[i] = __float2half(W1[i]);
    __syncthreads();

    const int lane = tid & 31, warp = tid >> 5;
    const int gid = lane >> 2, tig = lane & 3;

    // Preload B fragments: b[kk][nt][0] = rows tig*2, tig*2+1 ; [1] = +8,+9
    unsigned bfr[8][2][2];
#pragma unroll
    for (int kk = 0; kk < 8; ++kk) {
#pragma unroll
        for (int nt = 0; nt < 2; ++nt) {
            int k0 = kk * 16 + tig * 2;
            int col = nt * 8 + gid;
            __half2 lo = __halves2half2(w1h[k0 * 16 + col], w1h[(k0 + 1) * 16 + col]);
            __half2 hi = __halves2half2(w1h[(k0 + 8) * 16 + col], w1h[(k0 + 9) * 16 + col]);
            bfr[kk][nt][0] = *(unsigned*)&lo;
            bfr[kk][nt][1] = *(unsigned*)&hi;
        }
    }

    int tile = blockIdx.x * 8 + warp;
    int row0 = tile * 16;
    if (row0 >= n) return;
    __half* xt = xs[warp];

    // stage 16 rows x 128 halfs (1 coalesced LDG.128 per lane per row)
#pragma unroll 4
    for (int r = 0; r < 16; ++r) {
        int row = row0 + r;
        float4 v = make_float4(0.f, 0.f, 0.f, 0.f);
        if (row < n) v = ((const float4*)x)[(size_t)row * 32 + lane];
        __half2 h0 = __floats2half2_rn(v.x, v.y);
        __half2 h1 = __floats2half2_rn(v.z, v.w);
        *(__half2*)&xt[r * 136 + lane * 4]     = h0;
        *(__half2*)&xt[r * 136 + lane * 4 + 2] = h1;
    }
    __syncwarp();

    float c0[4] = {0.f, 0.f, 0.f, 0.f};
    float c1[4] = {0.f, 0.f, 0.f, 0.f};
#pragma unroll
    for (int kk = 0; kk < 8; ++kk) {
        int kb = kk * 16 + tig * 2;
        unsigned a0 = *(unsigned*)&xt[gid * 136 + kb];
        unsigned a1 = *(unsigned*)&xt[(gid + 8) * 136 + kb];
        unsigned a2 = *(unsigned*)&xt[gid * 136 + kb + 8];
        unsigned a3 = *(unsigned*)&xt[(gid + 8) * 136 + kb + 8];
        asm volatile(
            "mma.sync.aligned.m16n8k16.row.col.f32.f16.f16.f32 "
            "{%0,%1,%2,%3}, {%4,%5,%6,%7}, {%8,%9}, {%0,%1,%2,%3};"
            : "+f"(c0[0]), "+f"(c0[1]), "+f"(c0[2]), "+f"(c0[3])
            : "r"(a0), "r"(a1), "r"(a2), "r"(a3),
              "r"(bfr[kk][0][0]), "r"(bfr[kk][0][1]));
        asm volatile(
            "mma.sync.aligned.m16n8k16.row.col.f32.f16.f16.f32 "
            "{%0,%1,%2,%3}, {%4,%5,%6,%7}, {%8,%9}, {%0,%1,%2,%3};"
            : "+f"(c1[0]), "+f"(c1[1]), "+f"(c1[2]), "+f"(c1[3])
            : "r"(a0), "r"(a1), "r"(a2), "r"(a3),
              "r"(bfr[kk][1][0]), "r"(bfr[kk][1][1]));
    }

    // epilogue: C layout c0,c1 @ row=gid cols tig*2,+1 ; c2,c3 @ row+8
    int rA = row0 + gid, rB = row0 + gid + 8;
    float dvA = (rA < n) ? g_dinv[rA] : 0.f;
    float dvB = (rB < n) ? g_dinv[rB] : 0.f;
    if (rA < n) {
        __half2 vA0 = __floats2half2_rn(c0[0] * dvA, c0[1] * dvA);
        __half2 vA1 = __floats2half2_rn(c1[0] * dvA, c1[1] * dvA);
        *(__half2*)&g_g1h[(size_t)rA * 16 + tig * 2]     = vA0;
        *(__half2*)&g_g1h[(size_t)rA * 16 + 8 + tig * 2] = vA1;
    }
    if (rB < n) {
        __half2 vB0 = __floats2half2_rn(c0[2] * dvB, c0[3] * dvB);
        __half2 vB1 = __floats2half2_rn(c1[2] * dvB, c1[3] * dvB);
        *(__half2*)&g_g1h[(size_t)rB * 16 + tig * 2]     = vB0;
        *(__half2*)&g_g1h[(size_t)rB * 16 + 8 + tig * 2] = vB1;
    }
}

// ---- gather: warp per node, 4-lane edge groups over fp16 rows, 4-deep
// independent loads per lane, fp32 accumulate, butterfly reduce. ----
template <int LAYER>
__global__ __launch_bounds__(256) void gather_kernel(int n) {
    const __half* __restrict__ in = (LAYER == 0) ? g_g1h : g_g2h;
    float* __restrict__ out       = (LAYER == 0) ? g_tmp1 : g_tmp2;
    const int stride = (LAYER == 0) ? HID : CPH;
    const int nq     = (LAYER == 0) ? 4 : 3;

    int gw = (blockIdx.x * 256 + threadIdx.x) >> 5;
    if (gw >= n) return;
    int lane = threadIdx.x & 31;
    int eq = lane >> 2, q = lane & 3;
    int m = g_cnt[gw];
    const int* cs = g_csr + g_base[gw];

    float4 acc = make_float4(0.f, 0.f, 0.f, 0.f);
    if (q < nq) {
        int j = eq;
        for (; j + 24 < m; j += 32) {
            int s0 = cs[j], s1 = cs[j + 8], s2 = cs[j + 16], s3 = cs[j + 24];
            uint2 v0 = *(const uint2*)(in + (size_t)s0 * stride + q * 4);
            uint2 v1 = *(const uint2*)(in + (size_t)s1 * stride + q * 4);
            uint2 v2 = *(const uint2*)(in + (size_t)s2 * stride + q * 4);
            uint2 v3 = *(const uint2*)(in + (size_t)s3 * stride + q * 4);
            float2 f;
            f = __half22float2(*(const __half2*)&v0.x); acc.x += f.x; acc.y += f.y;
            f = __half22float2(*(const __half2*)&v0.y); acc.z += f.x; acc.w += f.y;
            f = __half22float2(*(const __half2*)&v1.x); acc.x += f.x; acc.y += f.y;
            f = __half22float2(*(const __half2*)&v1.y); acc.z += f.x; acc.w += f.y;
            f = __half22float2(*(const __half2*)&v2.x); acc.x += f.x; acc.y += f.y;
            f = __half22float2(*(const __half2*)&v2.y); acc.z += f.x; acc.w += f.y;
            f = __half22float2(*(const __half2*)&v3.x); acc.x += f.x; acc.y += f.y;
            f = __half22float2(*(const __half2*)&v3.y); acc.z += f.x; acc.w += f.y;
        }
        for (; j < m; j += 8) {
            int s = cs[j];
            uint2 va = *(const uint2*)(in + (size_t)s * stride + q * 4);
            float2 f;
            f = __half22float2(*(const __half2*)&va.x); acc.x += f.x; acc.y += f.y;
            f = __half22float2(*(const __half2*)&va.y); acc.z += f.x; acc.w += f.y;
        }
    }
#pragma unroll
    for (int st = 4; st < 32; st <<= 1) {
        acc.x += __shfl_xor_sync(~0u, acc.x, st);
        acc.y += __shfl_xor_sync(~0u, acc.y, st);
        acc.z += __shfl_xor_sync(~0u, acc.z, st);
        acc.w += __shfl_xor_sync(~0u, acc.w, st);
    }
    if (lane < nq)
        *(float4*)(out + (size_t)gw * stride + q * 4) = acc;
}

// ---- finalize layer1 + GEMM2: h=relu(dinv*(tmp1+g1)+b1); g2h=fp16((h@W2)*dinv) ----
__global__ __launch_bounds__(256) void fin1_kernel(const float* __restrict__ b1,
                                                   const float* __restrict__ W2,
                                                   int n) {
    __shared__ float w2s[HID * NC];
    __shared__ float b1s[HID];
    int tid = threadIdx.x;
    if (tid < HID * NC) w2s[tid] = W2[tid];
    if (tid < HID)      b1s[tid] = b1[tid];
    __syncthreads();

    int i = blockIdx.x * 256 + tid;
    if (i >= n) return;
    float dv = g_dinv[i];

    float h[16];
    const float4* tp = (const float4*)(g_tmp1 + (size_t)i * HID);
    const __half2* gp = (const __half2*)(g_g1h + (size_t)i * HID);
#pragma unroll
    for (int o4 = 0; o4 < 4; ++o4) {
        float4 t = tp[o4];
        float2 ga = __half22float2(gp[o4 * 2]);
        float2 gb = __half22float2(gp[o4 * 2 + 1]);
        h[o4 * 4 + 0] = fmaxf(fmaf(dv, t.x + ga.x, b1s[o4 * 4 + 0]), 0.f);
        h[o4 * 4 + 1] = fmaxf(fmaf(dv, t.y + ga.y, b1s[o4 * 4 + 1]), 0.f);
        h[o4 * 4 + 2] = fmaxf(fmaf(dv, t.z + gb.x, b1s[o4 * 4 + 2]), 0.f);
        h[o4 * 4 + 3] = fmaxf(fmaf(dv, t.w + gb.y, b1s[o4 * 4 + 3]), 0.f);
    }

    float acc[NC];
#pragma unroll
    for (int c = 0; c < NC; ++c) acc[c] = 0.f;
#pragma unroll
    for (int o = 0; o < HID; ++o) {
        float hv = h[o];
#pragma unroll
        for (int c = 0; c < NC; ++c) acc[c] = fmaf(hv, w2s[o * NC + c], acc[c]);
    }

    __half2 p[6];
#pragma unroll
    for (int c = 0; c < 5; ++c)
        p[c] = __floats2half2_rn(acc[c * 2] * dv, acc[c * 2 + 1] * dv);
    p[5] = __floats2half2_rn(0.f, 0.f);
    uint2* out = (uint2*)(g_g2h + (size_t)i * CPH);
    out[0] = *(uint2*)&p[0];
    out[1] = *(uint2*)&p[2];
    out[2] = *(uint2*)&p[4];
}

// ---- finalize layer2 + softmax ----
__global__ __launch_bounds__(256) void fin2_kernel(const float* __restrict__ b2,
                                                   float* __restrict__ out, int n) {
    __shared__ float b2s[NC];
    if (threadIdx.x < NC) b2s[threadIdx.x] = b2[threadIdx.x];
    __syncthreads();
    int i = blockIdx.x * blockDim.x + threadIdx.x;
    if (i >= n) return;
    float dv = g_dinv[i];
    const float* tp = g_tmp2 + (size_t)i * CPH;
    const __half2* gp = (const __half2*)(g_g2h + (size_t)i * CPH);
    float g[10];
#pragma unroll
    for (int c = 0; c < 5; ++c) {
        float2 f = __half22float2(gp[c]);
        g[c * 2] = f.x; g[c * 2 + 1] = f.y;
    }
    float l[NC];
    float m = -1e30f;
#pragma unroll
    for (int c = 0; c < NC; ++c) {
        l[c] = fmaf(dv, tp[c] + g[c], b2s[c]);
        m = fmaxf(m, l[c]);
    }
    float sum = 0.f;
#pragma unroll
    for (int c = 0; c < NC; ++c) {
        l[c] = expf(l[c] - m);
        sum += l[c];
    }
    float inv = 1.0f / sum;
#pragma unroll
    for (int c = 0; c < NC; ++c) out[i * NC + c] = l[c] * inv;
}

// ---------------------------------------------------------------
extern "C" void kernel_launch(void* const* d_in, const int* in_sizes, int n_in,
                              void* d_out, int out_size) {
    const float* x  = (const float*)d_in[0];
    const int*   ei = (const int*)  d_in[1];
    const float* W1 = (const float*)d_in[2];
    const float* b1 = (const float*)d_in[3];
    const float* W2 = (const float*)d_in[4];
    const float* b2 = (const float*)d_in[5];
    float* out = (float*)d_out;

    int n = in_sizes[0] / F_IN;
    int e = in_sizes[1] / 2;
    const int* src = ei;
    const int* dst = ei + e;
    int nb = (n + 255) / 256;

    bool aligned = ((e & 3) == 0) &&
                   ((((size_t)src) & 15) == 0) && ((((size_t)dst) & 15) == 0);

    zero_kernel <<<nb, 256>>>(n);
    if (aligned) {
        int t = (e >> 2);
        deg_kernel_v<<<(t + 255) / 256, 256>>>(dst, e);
    } else {
        deg_kernel_s<<<(e + 255) / 256, 256>>>(dst, e);
    }
    scan1_kernel<<<nb, 256>>>(n);
    scan3_kernel<<<nb, 256>>>(n);
    if (aligned) {
        int t = (e >> 2);
        place_kernel_v<<<(t + 255) / 256, 256>>>(src, dst, e);
    } else {
        place_kernel_s<<<(e + 255) / 256, 256>>>(src, dst, e);
    }
    int ntiles = (n + 15) / 16;
    gemm1_kernel<<<(ntiles + 7) / 8, 256>>>(x, W1, n);
    gather_kernel<0><<<(n * 32 + 255) / 256, 256>>>(n);
    fin1_kernel <<<nb, 256>>>(b1, W2, n);
    gather_kernel<1><<<(n * 32 + 255) / 256, 256>>>(n);
    fin2_kernel <<<nb, 256>>>(b2, out, n);
}